// round 1
// baseline (speedup 1.0000x reference)
#include <cuda_runtime.h>

// Problem constants (fixed by setup_inputs)
#define B        8
#define KN       768          // K*N rand_over points per batch
#define BETA_N   192          // top-k selected
#define NCOV     64           // rand_cov points
#define NPTS     256          // BETA_N + NCOV
#define C_OUT    128
#define H_OUT    256
#define HW_OUT   (256*256)
#define C_RES    64
#define H_RES    512
#define HW_RES   (512*512)
#define C_FEAT   192
#define REND_ELEMS (B*C_OUT*NPTS)   // 262144

__device__ float g_unc[B * KN];

// ------------------------------------------------------------------
// Kernel A: per-point uncertainty = -(top1 - top2) bilinearly sampled
// grid (96, 8), block 256 (8 warps), one warp per point
// ------------------------------------------------------------------
__global__ void unc_kernel(const float* __restrict__ outp,
                           const float* __restrict__ rand_over) {
    int b    = blockIdx.y;
    int warp = threadIdx.x >> 5;
    int lane = threadIdx.x & 31;
    int p    = blockIdx.x * 8 + warp;   // 0..767

    const float* rnd = rand_over + ((size_t)b * KN + p) * 2;
    float px = rnd[0], py = rnd[1];

    // gx = px*W - 0.5 with NO fma contraction (match XLA op-by-op rounding)
    float gx = __fadd_rn(__fmul_rn(px, 256.0f), -0.5f);
    float gy = __fadd_rn(__fmul_rn(py, 256.0f), -0.5f);
    float x0f = floorf(gx), y0f = floorf(gy);
    float wx = __fadd_rn(gx, -x0f);
    float wy = __fadd_rn(gy, -y0f);
    int x0 = (int)x0f, y0 = (int)y0f;

    int   pix[4];
    float vld[4];
#pragma unroll
    for (int j = 0; j < 4; j++) {
        int xi = x0 + (j & 1), yi = y0 + (j >> 1);
        vld[j] = (xi >= 0 && xi < 256 && yi >= 0 && yi < 256) ? 1.0f : 0.0f;
        int cx = min(max(xi, 0), 255), cy = min(max(yi, 0), 255);
        pix[j] = cy * 256 + cx;
    }

    const float* ob = outp + (size_t)b * C_OUT * HW_OUT;
    float vals[16];
    // issue all 16 loads first: MLP=16
#pragma unroll
    for (int j = 0; j < 4; j++)
#pragma unroll
        for (int k = 0; k < 4; k++)
            vals[j * 4 + k] = __ldg(ob + (size_t)(lane + k * 32) * HW_OUT + pix[j]);

    float m1c[4], m2c[4];
#pragma unroll
    for (int j = 0; j < 4; j++) {
        float m1 = vals[j * 4], m2 = -3.4e38f;
#pragma unroll
        for (int k = 1; k < 4; k++) {
            float v  = vals[j * 4 + k];
            float hi = fmaxf(m1, v), lo = fminf(m1, v);
            m2 = fmaxf(m2, lo);
            m1 = hi;
        }
#pragma unroll
        for (int off = 16; off; off >>= 1) {
            float o1 = __shfl_xor_sync(0xffffffffu, m1, off);
            float o2 = __shfl_xor_sync(0xffffffffu, m2, off);
            float hi = fmaxf(m1, o1), lo = fminf(m1, o1);
            m2 = fmaxf(lo, fmaxf(m2, o2));
            m1 = hi;
        }
        m1c[j] = m1; m2c[j] = m2;
    }

    if (lane == 0) {
        float omx = __fadd_rn(1.0f, -wx);
        float omy = __fadd_rn(1.0f, -wy);
        // v = corner * valid, then (((t00 + t01) + t10) + t11), t = (v*cx)*cy
        float v0, t, og0, og1;
        // channel 0 (top1)
        v0 = __fmul_rn(m1c[0], vld[0]); t = __fmul_rn(__fmul_rn(v0, omx), omy); og0 = t;
        v0 = __fmul_rn(m1c[1], vld[1]); t = __fmul_rn(__fmul_rn(v0, wx),  omy); og0 = __fadd_rn(og0, t);
        v0 = __fmul_rn(m1c[2], vld[2]); t = __fmul_rn(__fmul_rn(v0, omx), wy);  og0 = __fadd_rn(og0, t);
        v0 = __fmul_rn(m1c[3], vld[3]); t = __fmul_rn(__fmul_rn(v0, wx),  wy);  og0 = __fadd_rn(og0, t);
        // channel 1 (top2)
        v0 = __fmul_rn(m2c[0], vld[0]); t = __fmul_rn(__fmul_rn(v0, omx), omy); og1 = t;
        v0 = __fmul_rn(m2c[1], vld[1]); t = __fmul_rn(__fmul_rn(v0, wx),  omy); og1 = __fadd_rn(og1, t);
        v0 = __fmul_rn(m2c[2], vld[2]); t = __fmul_rn(__fmul_rn(v0, omx), wy);  og1 = __fadd_rn(og1, t);
        v0 = __fmul_rn(m2c[3], vld[3]); t = __fmul_rn(__fmul_rn(v0, wx),  wy);  og1 = __fadd_rn(og1, t);
        // uncertainty = -(og0 - og1)
        g_unc[b * KN + p] = -__fadd_rn(og0, -og1);
    }
}

// ------------------------------------------------------------------
// Kernel B: per-batch stable top-192 via bitonic sort of 1024 keys,
// then write the points output block of d_out.
// grid 8, block 1024
// ------------------------------------------------------------------
__global__ void sort_kernel(const float* __restrict__ rand_over,
                            const float* __restrict__ rand_cov,
                            float* __restrict__ dout) {
    __shared__ unsigned long long key[1024];
    int b = blockIdx.x;
    int t = threadIdx.x;

    unsigned long long k0 = ~0ULL;   // padding sorts last
    if (t < KN) {
        float u = g_unc[b * KN + t];
        unsigned ub = __float_as_uint(u);
        ub = (ub & 0x80000000u) ? ~ub : (ub | 0x80000000u); // ascending-sortable
        ub = ~ub;                                           // now descending value
        k0 = ((unsigned long long)ub << 32) | (unsigned)t;  // tie: ascending index
    }
    key[t] = k0;
    __syncthreads();

    for (int k = 2; k <= 1024; k <<= 1) {
        for (int j = k >> 1; j > 0; j >>= 1) {
            int ix = t ^ j;
            if (ix > t) {
                unsigned long long a = key[t], c = key[ix];
                bool up = ((t & k) == 0);
                if ((a > c) == up) { key[t] = c; key[ix] = a; }
            }
            __syncthreads();
        }
    }

    float* pts = dout + REND_ELEMS;
    if (t < BETA_N) {
        int idx = (int)(key[t] & 0xFFFFFFFFu);
        pts[((size_t)b * NPTS + t) * 2 + 0] = rand_over[((size_t)b * KN + idx) * 2 + 0];
        pts[((size_t)b * NPTS + t) * 2 + 1] = rand_over[((size_t)b * KN + idx) * 2 + 1];
    } else if (t < NPTS) {
        int j2 = t - BETA_N;
        pts[((size_t)b * NPTS + t) * 2 + 0] = rand_cov[((size_t)b * NCOV + j2) * 2 + 0];
        pts[((size_t)b * NPTS + t) * 2 + 1] = rand_cov[((size_t)b * NCOV + j2) * 2 + 1];
    }
}

// ------------------------------------------------------------------
// Kernel C: gather 192-ch features at 32 points, 128x192 GEMV tile
// grid (8 point-tiles, 8 batches), block 256
// dynamic smem: weight[128*192] + feat[192][32]
// ------------------------------------------------------------------
__device__ __forceinline__ float bilin(const float* __restrict__ plane, int HW1,
                                       int x0, int y0, float wx, float wy) {
    // HW1 = H = W (square)
    float r = 0.0f;
#pragma unroll
    for (int j = 0; j < 4; j++) {
        int xi = x0 + (j & 1), yi = y0 + (j >> 1);
        if (xi >= 0 && xi < HW1 && yi >= 0 && yi < HW1) {
            float cf = ((j & 1) ? wx : 1.0f - wx) * ((j >> 1) ? wy : 1.0f - wy);
            r = fmaf(cf, __ldg(plane + (size_t)yi * HW1 + xi), r);
        }
    }
    return r;
}

__global__ void rend_kernel(const float* __restrict__ outp,
                            const float* __restrict__ res2,
                            const float* __restrict__ weight,
                            const float* __restrict__ bias,
                            float* __restrict__ dout) {
    extern __shared__ float sm[];
    float* wsh = sm;             // 128*192 = 24576 floats
    float* fsh = sm + 24576;     // 192*32  = 6144 floats  (layout [c][p])

    __shared__ int   x0a[32], y0a[32], x0b[32], y0b[32];
    __shared__ float wxa[32], wya[32], wxb[32], wyb[32];

    int b = blockIdx.y, ptile = blockIdx.x;
    int tid = threadIdx.x;

    const float* pts = dout + REND_ELEMS + ((size_t)b * NPTS + ptile * 32) * 2;
    if (tid < 32) {
        float px = pts[tid * 2 + 0], py = pts[tid * 2 + 1];
        {
            float gx = px * 256.0f - 0.5f, gy = py * 256.0f - 0.5f;
            float xf = floorf(gx), yf = floorf(gy);
            x0a[tid] = (int)xf; y0a[tid] = (int)yf;
            wxa[tid] = gx - xf; wya[tid] = gy - yf;
        }
        {
            float gx = px * 512.0f - 0.5f, gy = py * 512.0f - 0.5f;
            float xf = floorf(gx), yf = floorf(gy);
            x0b[tid] = (int)xf; y0b[tid] = (int)yf;
            wxb[tid] = gx - xf; wyb[tid] = gy - yf;
        }
    }
    for (int i = tid; i < C_OUT * C_FEAT; i += 256) wsh[i] = weight[i];
    __syncthreads();

    // gather: v = c*32 + p, 24 values per thread
#pragma unroll 4
    for (int vv = 0; vv < 24; vv++) {
        int v = vv * 256 + tid;
        int p = v & 31, c = v >> 5;
        float r;
        if (c < C_OUT) {
            const float* plane = outp + (size_t)(b * C_OUT + c) * HW_OUT;
            r = bilin(plane, 256, x0a[p], y0a[p], wxa[p], wya[p]);
        } else {
            const float* plane = res2 + (size_t)(b * C_RES + (c - C_OUT)) * HW_RES;
            r = bilin(plane, 512, x0b[p], y0b[p], wxb[p], wyb[p]);
        }
        fsh[v] = r;
    }
    __syncthreads();

    // GEMV tile: thread -> (chunk of 16 outputs, point p)
    int p = tid & 31, chunk = tid >> 5;            // chunk 0..7
    const float* wrow = wsh + (chunk * 16) * C_FEAT;
    float acc[16];
#pragma unroll
    for (int i = 0; i < 16; i++) acc[i] = __ldg(bias + chunk * 16 + i);
    for (int c = 0; c < C_FEAT; c++) {
        float f = fsh[c * 32 + p];
#pragma unroll
        for (int i = 0; i < 16; i++)
            acc[i] = fmaf(wrow[i * C_FEAT + c], f, acc[i]);
    }
    float* rend = dout + (size_t)b * C_OUT * NPTS + ptile * 32 + p;
#pragma unroll
    for (int i = 0; i < 16; i++)
        rend[(size_t)(chunk * 16 + i) * NPTS] = acc[i];
}

// ------------------------------------------------------------------
extern "C" void kernel_launch(void* const* d_in, const int* in_sizes, int n_in,
                              void* d_out, int out_size) {
    (void)in_sizes; (void)n_in; (void)out_size;
    // inputs: x, res2, out, rand_over, rand_cov, weight, bias
    const float* res2      = (const float*)d_in[1];
    const float* outp      = (const float*)d_in[2];
    const float* rand_over = (const float*)d_in[3];
    const float* rand_cov  = (const float*)d_in[4];
    const float* weight    = (const float*)d_in[5];
    const float* bias      = (const float*)d_in[6];
    float* dout = (float*)d_out;

    unc_kernel<<<dim3(96, B), 256>>>(outp, rand_over);
    sort_kernel<<<B, 1024>>>(rand_over, rand_cov, dout);

    size_t smem = (size_t)(24576 + 6144) * sizeof(float);   // 122880 B
    cudaFuncSetAttribute(rend_kernel, cudaFuncAttributeMaxDynamicSharedMemorySize,
                         (int)smem);
    rend_kernel<<<dim3(8, B), 256, smem>>>(outp, res2, weight, bias, dout);
}

// round 2
// speedup vs baseline: 1.1107x; 1.1107x over previous
#include <cuda_runtime.h>

#define B        8
#define KN       768
#define BETA_N   192
#define NCOV     64
#define NPTS     256
#define C_OUT    128
#define HW_OUT   (256*256)
#define C_RES    64
#define HW_RES   (512*512)
#define C_FEAT   192
#define REND_ELEMS (B*C_OUT*NPTS)   // 262144

__device__ float g_unc[B * KN];
__device__ float g_coarse[(size_t)B * KN * C_OUT];  // cached bilinear out-features per rand_over point
__device__ int   g_selidx[B * BETA_N];

// ------------------------------------------------------------------
// Kernel A: uncertainty + cached 128-ch coarse features per point
// grid (96, 8), block 256, one warp per point
// ------------------------------------------------------------------
__global__ void unc_kernel(const float* __restrict__ outp,
                           const float* __restrict__ rand_over) {
    int b    = blockIdx.y;
    int warp = threadIdx.x >> 5;
    int lane = threadIdx.x & 31;
    int p    = blockIdx.x * 8 + warp;   // 0..767

    const float* rnd = rand_over + ((size_t)b * KN + p) * 2;
    float px = rnd[0], py = rnd[1];

    // exact op-order match with XLA (no fma contraction) for the top-k path
    float gx = __fadd_rn(__fmul_rn(px, 256.0f), -0.5f);
    float gy = __fadd_rn(__fmul_rn(py, 256.0f), -0.5f);
    float x0f = floorf(gx), y0f = floorf(gy);
    float wx = __fadd_rn(gx, -x0f);
    float wy = __fadd_rn(gy, -y0f);
    int x0 = (int)x0f, y0 = (int)y0f;

    int   pix[4];
    float vld[4];
#pragma unroll
    for (int j = 0; j < 4; j++) {
        int xi = x0 + (j & 1), yi = y0 + (j >> 1);
        vld[j] = (xi >= 0 && xi < 256 && yi >= 0 && yi < 256) ? 1.0f : 0.0f;
        int cx = min(max(xi, 0), 255), cy = min(max(yi, 0), 255);
        pix[j] = cy * 256 + cx;
    }

    const float* ob = outp + (size_t)b * C_OUT * HW_OUT;
    float vals[16];
#pragma unroll
    for (int j = 0; j < 4; j++)
#pragma unroll
        for (int k = 0; k < 4; k++)
            vals[j * 4 + k] = __ldg(ob + (size_t)(lane + k * 32) * HW_OUT + pix[j]);

    // ---- cached coarse features (tolerance path, fma ok) ----
    {
        float omx = 1.0f - wx, omy = 1.0f - wy;
        float cw[4];
        cw[0] = omx * omy * vld[0];
        cw[1] = wx  * omy * vld[1];
        cw[2] = omx * wy  * vld[2];
        cw[3] = wx  * wy  * vld[3];
        float* cc = g_coarse + ((size_t)b * KN + p) * C_OUT + lane;
#pragma unroll
        for (int k = 0; k < 4; k++) {
            float r = vals[k] * cw[0];
            r = fmaf(vals[4 + k],  cw[1], r);
            r = fmaf(vals[8 + k],  cw[2], r);
            r = fmaf(vals[12 + k], cw[3], r);
            cc[k * 32] = r;
        }
    }

    // ---- top-2 across 128 channels per corner ----
    float m1c[4], m2c[4];
#pragma unroll
    for (int j = 0; j < 4; j++) {
        float m1 = vals[j * 4], m2 = -3.4e38f;
#pragma unroll
        for (int k = 1; k < 4; k++) {
            float v  = vals[j * 4 + k];
            float hi = fmaxf(m1, v), lo = fminf(m1, v);
            m2 = fmaxf(m2, lo);
            m1 = hi;
        }
#pragma unroll
        for (int off = 16; off; off >>= 1) {
            float o1 = __shfl_xor_sync(0xffffffffu, m1, off);
            float o2 = __shfl_xor_sync(0xffffffffu, m2, off);
            float hi = fmaxf(m1, o1), lo = fminf(m1, o1);
            m2 = fmaxf(lo, fmaxf(m2, o2));
            m1 = hi;
        }
        m1c[j] = m1; m2c[j] = m2;
    }

    if (lane == 0) {
        float omx = __fadd_rn(1.0f, -wx);
        float omy = __fadd_rn(1.0f, -wy);
        float v0, t, og0, og1;
        v0 = __fmul_rn(m1c[0], vld[0]); t = __fmul_rn(__fmul_rn(v0, omx), omy); og0 = t;
        v0 = __fmul_rn(m1c[1], vld[1]); t = __fmul_rn(__fmul_rn(v0, wx),  omy); og0 = __fadd_rn(og0, t);
        v0 = __fmul_rn(m1c[2], vld[2]); t = __fmul_rn(__fmul_rn(v0, omx), wy);  og0 = __fadd_rn(og0, t);
        v0 = __fmul_rn(m1c[3], vld[3]); t = __fmul_rn(__fmul_rn(v0, wx),  wy);  og0 = __fadd_rn(og0, t);
        v0 = __fmul_rn(m2c[0], vld[0]); t = __fmul_rn(__fmul_rn(v0, omx), omy); og1 = t;
        v0 = __fmul_rn(m2c[1], vld[1]); t = __fmul_rn(__fmul_rn(v0, wx),  omy); og1 = __fadd_rn(og1, t);
        v0 = __fmul_rn(m2c[2], vld[2]); t = __fmul_rn(__fmul_rn(v0, omx), wy);  og1 = __fadd_rn(og1, t);
        v0 = __fmul_rn(m2c[3], vld[3]); t = __fmul_rn(__fmul_rn(v0, wx),  wy);  og1 = __fadd_rn(og1, t);
        g_unc[b * KN + p] = -__fadd_rn(og0, -og1);
    }
}

// ------------------------------------------------------------------
// Kernel B: stable top-192 per batch (bitonic, 64-bit keys) + points out
// ------------------------------------------------------------------
__global__ void sort_kernel(const float* __restrict__ rand_over,
                            const float* __restrict__ rand_cov,
                            float* __restrict__ dout) {
    __shared__ unsigned long long key[1024];
    int b = blockIdx.x;
    int t = threadIdx.x;

    unsigned long long k0 = ~0ULL;
    if (t < KN) {
        float u = g_unc[b * KN + t];
        unsigned ub = __float_as_uint(u);
        ub = (ub & 0x80000000u) ? ~ub : (ub | 0x80000000u);
        ub = ~ub;
        k0 = ((unsigned long long)ub << 32) | (unsigned)t;
    }
    key[t] = k0;
    __syncthreads();

    for (int k = 2; k <= 1024; k <<= 1) {
        for (int j = k >> 1; j > 0; j >>= 1) {
            int ix = t ^ j;
            if (ix > t) {
                unsigned long long a = key[t], c = key[ix];
                bool up = ((t & k) == 0);
                if ((a > c) == up) { key[t] = c; key[ix] = a; }
            }
            __syncthreads();
        }
    }

    float* pts = dout + REND_ELEMS;
    if (t < BETA_N) {
        int idx = (int)(key[t] & 0xFFFFFFFFu);
        g_selidx[b * BETA_N + t] = idx;
        pts[((size_t)b * NPTS + t) * 2 + 0] = rand_over[((size_t)b * KN + idx) * 2 + 0];
        pts[((size_t)b * NPTS + t) * 2 + 1] = rand_over[((size_t)b * KN + idx) * 2 + 1];
    } else if (t < NPTS) {
        int j2 = t - BETA_N;
        pts[((size_t)b * NPTS + t) * 2 + 0] = rand_cov[((size_t)b * NCOV + j2) * 2 + 0];
        pts[((size_t)b * NPTS + t) * 2 + 1] = rand_cov[((size_t)b * NCOV + j2) * 2 + 1];
    }
}

// ------------------------------------------------------------------
// Kernel C: rend. 16-point tiles, 128 blocks (one wave), block 256.
// smem: wT[192][129] transposed weight + fsh[192][17] feat tile.
// ------------------------------------------------------------------
#define WPAD 129
#define FPAD 17
#define TILE 16
#define SMEM_BYTES ((C_FEAT*WPAD + C_FEAT*FPAD) * 4)

__global__ void rend_kernel(const float* __restrict__ outp,
                            const float* __restrict__ res2,
                            const float* __restrict__ weight,
                            const float* __restrict__ bias,
                            float* __restrict__ dout) {
    extern __shared__ float sm[];
    float* wsh = sm;                    // [c][o] padded row 129
    float* fsh = sm + C_FEAT * WPAD;    // [c][p] padded row 17

    __shared__ int   offA[TILE][4], offB[TILE][4];
    __shared__ float wA[TILE][4],  wB[TILE][4];

    int b = blockIdx.y, tile = blockIdx.x;           // tile 0..15
    bool is_cov = (tile >= 12);
    int tid = threadIdx.x;

    // --- per-point params ---
    if (tid < TILE) {
        const float* pts = dout + REND_ELEMS + ((size_t)b * NPTS + tile * TILE + tid) * 2;
        float px = pts[0], py = pts[1];
        if (is_cov) {   // need out-res params only for cov tiles
            float gx = px * 256.0f - 0.5f, gy = py * 256.0f - 0.5f;
            float xf = floorf(gx), yf = floorf(gy);
            int x0 = (int)xf, y0 = (int)yf;
            float fx = gx - xf, fy = gy - yf;
#pragma unroll
            for (int j = 0; j < 4; j++) {
                int xi = x0 + (j & 1), yi = y0 + (j >> 1);
                float v = (xi >= 0 && xi < 256 && yi >= 0 && yi < 256) ? 1.0f : 0.0f;
                offA[tid][j] = min(max(yi, 0), 255) * 256 + min(max(xi, 0), 255);
                wA[tid][j]   = ((j & 1) ? fx : 1.0f - fx) * ((j >> 1) ? fy : 1.0f - fy) * v;
            }
        }
        {
            float gx = px * 512.0f - 0.5f, gy = py * 512.0f - 0.5f;
            float xf = floorf(gx), yf = floorf(gy);
            int x0 = (int)xf, y0 = (int)yf;
            float fx = gx - xf, fy = gy - yf;
#pragma unroll
            for (int j = 0; j < 4; j++) {
                int xi = x0 + (j & 1), yi = y0 + (j >> 1);
                float v = (xi >= 0 && xi < 512 && yi >= 0 && yi < 512) ? 1.0f : 0.0f;
                offB[tid][j] = min(max(yi, 0), 511) * 512 + min(max(xi, 0), 511);
                wB[tid][j]   = ((j & 1) ? fx : 1.0f - fx) * ((j >> 1) ? fy : 1.0f - fy) * v;
            }
        }
    }

    // --- stage weight transposed: wsh[c*129+o] = weight[o*192+c] ---
    {
        const float4* w4 = (const float4*)weight;   // 6144 float4
#pragma unroll
        for (int i = 0; i < 24; i++) {
            int idx = i * 256 + tid;
            int o = idx / 48, rem = idx - o * 48;
            float4 v = __ldg(w4 + idx);
            int cb = rem * 4;
            wsh[(cb + 0) * WPAD + o] = v.x;
            wsh[(cb + 1) * WPAD + o] = v.y;
            wsh[(cb + 2) * WPAD + o] = v.z;
            wsh[(cb + 3) * WPAD + o] = v.w;
        }
    }
    __syncthreads();

    // --- gather features into fsh ---
    if (!is_cov) {
        // coarse: cached, coalesced. 128 c x 16 p = 2048 vals, 8 iters
        const int* sel = g_selidx + b * BETA_N + tile * TILE;
#pragma unroll
        for (int i = 0; i < 8; i++) {
            int v = i * 256 + tid;
            int c = v & 127, p = v >> 7;
            fsh[c * FPAD + p] = __ldg(g_coarse + ((size_t)b * KN + sel[p]) * C_OUT + c);
        }
    } else {
        // out gather: 128 c x 16 p, 8 iters
#pragma unroll 4
        for (int i = 0; i < 8; i++) {
            int v = i * 256 + tid;
            int p = v & 15, c = v >> 4;
            const float* plane = outp + (size_t)(b * C_OUT + c) * HW_OUT;
            float r =        wA[p][0] * __ldg(plane + offA[p][0]);
            r = fmaf(wA[p][1], __ldg(plane + offA[p][1]), r);
            r = fmaf(wA[p][2], __ldg(plane + offA[p][2]), r);
            r = fmaf(wA[p][3], __ldg(plane + offA[p][3]), r);
            fsh[c * FPAD + p] = r;
        }
    }
    // res2 gather: 64 c x 16 p, 4 iters
#pragma unroll 4
    for (int i = 0; i < 4; i++) {
        int v = i * 256 + tid;
        int p = v & 15, c = v >> 4;
        const float* plane = res2 + (size_t)(b * C_RES + c) * HW_RES;
        float r =        wB[p][0] * __ldg(plane + offB[p][0]);
        r = fmaf(wB[p][1], __ldg(plane + offB[p][1]), r);
        r = fmaf(wB[p][2], __ldg(plane + offB[p][2]), r);
        r = fmaf(wB[p][3], __ldg(plane + offB[p][3]), r);
        fsh[(C_OUT + c) * FPAD + p] = r;
    }
    __syncthreads();

    // --- GEMV: thread = (o, point-group of 8) ---
    int o = tid & 127, pg = tid >> 7;
    float acc[8];
    float bv = __ldg(bias + o);
#pragma unroll
    for (int i = 0; i < 8; i++) acc[i] = bv;

    const float* fbase = fsh + pg * 8;
#pragma unroll 4
    for (int c = 0; c < C_FEAT; c++) {
        float w = wsh[c * WPAD + o];
        const float* f = fbase + c * FPAD;
#pragma unroll
        for (int i = 0; i < 8; i++)
            acc[i] = fmaf(w, f[i], acc[i]);
    }

    float* rp = dout + ((size_t)b * C_OUT + o) * NPTS + tile * TILE + pg * 8;
    float4* rp4 = (float4*)rp;
    rp4[0] = make_float4(acc[0], acc[1], acc[2], acc[3]);
    rp4[1] = make_float4(acc[4], acc[5], acc[6], acc[7]);
}

// ------------------------------------------------------------------
extern "C" void kernel_launch(void* const* d_in, const int* in_sizes, int n_in,
                              void* d_out, int out_size) {
    (void)in_sizes; (void)n_in; (void)out_size;
    const float* res2      = (const float*)d_in[1];
    const float* outp      = (const float*)d_in[2];
    const float* rand_over = (const float*)d_in[3];
    const float* rand_cov  = (const float*)d_in[4];
    const float* weight    = (const float*)d_in[5];
    const float* bias      = (const float*)d_in[6];
    float* dout = (float*)d_out;

    unc_kernel<<<dim3(96, B), 256>>>(outp, rand_over);
    sort_kernel<<<B, 1024>>>(rand_over, rand_cov, dout);

    cudaFuncSetAttribute(rend_kernel, cudaFuncAttributeMaxDynamicSharedMemorySize,
                         SMEM_BYTES);
    rend_kernel<<<dim3(16, B), 256, SMEM_BYTES>>>(outp, res2, weight, bias, dout);
}

// round 3
// speedup vs baseline: 1.2931x; 1.1641x over previous
#include <cuda_runtime.h>

#define B        8
#define KN       768
#define BETA_N   192
#define NCOV     64
#define NPTS     256
#define C_OUT    128
#define HW_OUT   (256*256)
#define C_RES    64
#define HW_RES   (512*512)
#define C_FEAT   192
#define REND_ELEMS (B*C_OUT*NPTS)   // 262144

__device__ float g_unc[B * KN];
__device__ float g_coarse[(size_t)B * KN * C_OUT];       // bilinear out-feats per rand_over pt
__device__ float g_covfeat[(size_t)B * C_FEAT * NCOV];   // full 192-ch feats for cov points
__device__ float g_wT[C_FEAT * C_OUT];                   // weight transposed [c][o]
__device__ int   g_selidx[B * BETA_N];

// ------------------------------------------------------------------
// Kernel A: grid (113, 8), block 256.
//  x <  96 : uncertainty + cached coarse features (1 warp / point)
//  96..111 : cov-point full feature gather (4 cov points / block)
//  x == 112: (b==0 only) weight transpose
// ------------------------------------------------------------------
__global__ void unc_kernel(const float* __restrict__ outp,
                           const float* __restrict__ res2,
                           const float* __restrict__ rand_over,
                           const float* __restrict__ rand_cov,
                           const float* __restrict__ weight) {
    int b   = blockIdx.y;
    int bx  = blockIdx.x;
    int tid = threadIdx.x;

    if (bx >= 96) {
        if (bx == 112) {
            // ---- weight transpose (one block) ----
            if (b != 0) return;
            const float4* w4 = (const float4*)weight;   // 6144 float4
#pragma unroll
            for (int i = 0; i < 24; i++) {
                int idx = i * 256 + tid;
                int o = idx / 48, rem = idx - o * 48;
                float4 v = __ldg(w4 + idx);
                int cb = rem * 4;
                g_wT[(cb + 0) * C_OUT + o] = v.x;
                g_wT[(cb + 1) * C_OUT + o] = v.y;
                g_wT[(cb + 2) * C_OUT + o] = v.z;
                g_wT[(cb + 3) * C_OUT + o] = v.w;
            }
            return;
        }
        // ---- cov feature gather: 4 points x 192 channels ----
        int g = bx - 96;                      // 0..15
#pragma unroll
        for (int i = 0; i < 3; i++) {
            int v  = i * 256 + tid;           // 0..767
            int jj = v & 3, c = v >> 2;       // point-in-group, channel
            int j  = g * 4 + jj;              // cov point 0..63
            float px = __ldg(rand_cov + ((size_t)b * NCOV + j) * 2 + 0);
            float py = __ldg(rand_cov + ((size_t)b * NCOV + j) * 2 + 1);
            const float* plane;
            int H;
            if (c < C_OUT) { plane = outp + (size_t)(b * C_OUT + c) * HW_OUT; H = 256; }
            else           { plane = res2 + (size_t)(b * C_RES + (c - C_OUT)) * HW_RES; H = 512; }
            float gx = px * (float)H - 0.5f, gy = py * (float)H - 0.5f;
            float xf = floorf(gx), yf = floorf(gy);
            int x0 = (int)xf, y0 = (int)yf;
            float fx = gx - xf, fy = gy - yf;
            float r = 0.0f;
#pragma unroll
            for (int q = 0; q < 4; q++) {
                int xi = x0 + (q & 1), yi = y0 + (q >> 1);
                if (xi >= 0 && xi < H && yi >= 0 && yi < H) {
                    float cf = ((q & 1) ? fx : 1.0f - fx) * ((q >> 1) ? fy : 1.0f - fy);
                    r = fmaf(cf, __ldg(plane + (size_t)yi * H + xi), r);
                }
            }
            g_covfeat[((size_t)b * C_FEAT + c) * NCOV + j] = r;
        }
        return;
    }

    // ---- uncertainty path (exact op-order, no fma contraction) ----
    int warp = tid >> 5, lane = tid & 31;
    int p = bx * 8 + warp;                    // 0..767

    const float* rnd = rand_over + ((size_t)b * KN + p) * 2;
    float px = rnd[0], py = rnd[1];

    float gx = __fadd_rn(__fmul_rn(px, 256.0f), -0.5f);
    float gy = __fadd_rn(__fmul_rn(py, 256.0f), -0.5f);
    float x0f = floorf(gx), y0f = floorf(gy);
    float wx = __fadd_rn(gx, -x0f);
    float wy = __fadd_rn(gy, -y0f);
    int x0 = (int)x0f, y0 = (int)y0f;

    int   pix[4];
    float vld[4];
#pragma unroll
    for (int j = 0; j < 4; j++) {
        int xi = x0 + (j & 1), yi = y0 + (j >> 1);
        vld[j] = (xi >= 0 && xi < 256 && yi >= 0 && yi < 256) ? 1.0f : 0.0f;
        int cx = min(max(xi, 0), 255), cy = min(max(yi, 0), 255);
        pix[j] = cy * 256 + cx;
    }

    const float* ob = outp + (size_t)b * C_OUT * HW_OUT;
    float vals[16];
#pragma unroll
    for (int j = 0; j < 4; j++)
#pragma unroll
        for (int k = 0; k < 4; k++)
            vals[j * 4 + k] = __ldg(ob + (size_t)(lane + k * 32) * HW_OUT + pix[j]);

    // cached coarse features (tolerance path)
    {
        float omx = 1.0f - wx, omy = 1.0f - wy;
        float cw[4] = { omx * omy * vld[0], wx * omy * vld[1],
                        omx * wy  * vld[2], wx * wy  * vld[3] };
        float* cc = g_coarse + ((size_t)b * KN + p) * C_OUT + lane;
#pragma unroll
        for (int k = 0; k < 4; k++) {
            float r = vals[k] * cw[0];
            r = fmaf(vals[4 + k],  cw[1], r);
            r = fmaf(vals[8 + k],  cw[2], r);
            r = fmaf(vals[12 + k], cw[3], r);
            cc[k * 32] = r;
        }
    }

    float m1c[4], m2c[4];
#pragma unroll
    for (int j = 0; j < 4; j++) {
        float m1 = vals[j * 4], m2 = -3.4e38f;
#pragma unroll
        for (int k = 1; k < 4; k++) {
            float v  = vals[j * 4 + k];
            float hi = fmaxf(m1, v), lo = fminf(m1, v);
            m2 = fmaxf(m2, lo);
            m1 = hi;
        }
#pragma unroll
        for (int off = 16; off; off >>= 1) {
            float o1 = __shfl_xor_sync(0xffffffffu, m1, off);
            float o2 = __shfl_xor_sync(0xffffffffu, m2, off);
            float hi = fmaxf(m1, o1), lo = fminf(m1, o1);
            m2 = fmaxf(lo, fmaxf(m2, o2));
            m1 = hi;
        }
        m1c[j] = m1; m2c[j] = m2;
    }

    if (lane == 0) {
        float omx = __fadd_rn(1.0f, -wx);
        float omy = __fadd_rn(1.0f, -wy);
        float v0, t, og0, og1;
        v0 = __fmul_rn(m1c[0], vld[0]); t = __fmul_rn(__fmul_rn(v0, omx), omy); og0 = t;
        v0 = __fmul_rn(m1c[1], vld[1]); t = __fmul_rn(__fmul_rn(v0, wx),  omy); og0 = __fadd_rn(og0, t);
        v0 = __fmul_rn(m1c[2], vld[2]); t = __fmul_rn(__fmul_rn(v0, omx), wy);  og0 = __fadd_rn(og0, t);
        v0 = __fmul_rn(m1c[3], vld[3]); t = __fmul_rn(__fmul_rn(v0, wx),  wy);  og0 = __fadd_rn(og0, t);
        v0 = __fmul_rn(m2c[0], vld[0]); t = __fmul_rn(__fmul_rn(v0, omx), omy); og1 = t;
        v0 = __fmul_rn(m2c[1], vld[1]); t = __fmul_rn(__fmul_rn(v0, wx),  omy); og1 = __fadd_rn(og1, t);
        v0 = __fmul_rn(m2c[2], vld[2]); t = __fmul_rn(__fmul_rn(v0, omx), wy);  og1 = __fadd_rn(og1, t);
        v0 = __fmul_rn(m2c[3], vld[3]); t = __fmul_rn(__fmul_rn(v0, wx),  wy);  og1 = __fadd_rn(og1, t);
        g_unc[b * KN + p] = -__fadd_rn(og0, -og1);
    }
}

// ------------------------------------------------------------------
// Kernel B: hybrid shfl/smem bitonic sort (stable top-192) + points out
// ------------------------------------------------------------------
__device__ __forceinline__ unsigned long long bstep(unsigned long long v,
                                                    unsigned long long u,
                                                    int t, int k, int j) {
    bool keep_min = (((t & k) == 0) == ((t & j) == 0));
    unsigned long long mn = v < u ? v : u;
    unsigned long long mx = v < u ? u : v;
    return keep_min ? mn : mx;
}

__global__ void sort_kernel(const float* __restrict__ rand_over,
                            const float* __restrict__ rand_cov,
                            float* __restrict__ dout) {
    __shared__ unsigned long long key[1024];
    int b = blockIdx.x;
    int t = threadIdx.x;

    unsigned long long v = ~0ULL;
    if (t < KN) {
        float u = g_unc[b * KN + t];
        unsigned ub = __float_as_uint(u);
        ub = (ub & 0x80000000u) ? ~ub : (ub | 0x80000000u);
        ub = ~ub;
        v = ((unsigned long long)ub << 32) | (unsigned)t;
    }

    // intra-warp stages k = 2..32 (shfl only)
#pragma unroll
    for (int k = 2; k <= 32; k <<= 1) {
#pragma unroll
        for (int j = k >> 1; j > 0; j >>= 1) {
            unsigned long long u = __shfl_xor_sync(0xffffffffu, v, j);
            v = bstep(v, u, t, k, j);
        }
    }
    // k = 64..1024: smem for j>=32, shfl for j<32
    for (int k = 64; k <= 1024; k <<= 1) {
        for (int j = k >> 1; j >= 32; j >>= 1) {
            key[t] = v;
            __syncthreads();
            unsigned long long u = key[t ^ j];
            v = bstep(v, u, t, k, j);
            __syncthreads();
        }
#pragma unroll
        for (int j = 16; j > 0; j >>= 1) {
            unsigned long long u = __shfl_xor_sync(0xffffffffu, v, j);
            v = bstep(v, u, t, k, j);
        }
    }

    float* pts = dout + REND_ELEMS;
    if (t < BETA_N) {
        int idx = (int)(v & 0xFFFFFFFFu);
        g_selidx[b * BETA_N + t] = idx;
        pts[((size_t)b * NPTS + t) * 2 + 0] = rand_over[((size_t)b * KN + idx) * 2 + 0];
        pts[((size_t)b * NPTS + t) * 2 + 1] = rand_over[((size_t)b * KN + idx) * 2 + 1];
    } else if (t < NPTS) {
        int j2 = t - BETA_N;
        pts[((size_t)b * NPTS + t) * 2 + 0] = rand_cov[((size_t)b * NCOV + j2) * 2 + 0];
        pts[((size_t)b * NPTS + t) * 2 + 1] = rand_cov[((size_t)b * NCOV + j2) * 2 + 1];
    }
}

// ------------------------------------------------------------------
// Kernel C: rend. grid (16, 8), block 256.
// smem: wsh[192*128] (96KB) + fsh[192][16] (12KB)
// ------------------------------------------------------------------
#define FPAD 16
#define TILE 16
#define SMEM_BYTES ((C_FEAT*C_OUT + C_FEAT*FPAD) * 4)

__global__ void rend_kernel(const float* __restrict__ res2,
                            const float* __restrict__ bias,
                            float* __restrict__ dout) {
    extern __shared__ float sm[];
    float* wsh = sm;                     // [c][o]
    float* fsh = sm + C_FEAT * C_OUT;    // [c][p], row 16

    __shared__ int   offB[TILE][4];
    __shared__ float wB[TILE][4];

    int b = blockIdx.y, tile = blockIdx.x;
    bool is_cov = (tile >= 12);
    int tid = threadIdx.x;

    if (!is_cov && tid < TILE) {
        const float* pts = dout + REND_ELEMS + ((size_t)b * NPTS + tile * TILE + tid) * 2;
        float px = pts[0], py = pts[1];
        float gx = px * 512.0f - 0.5f, gy = py * 512.0f - 0.5f;
        float xf = floorf(gx), yf = floorf(gy);
        int x0 = (int)xf, y0 = (int)yf;
        float fx = gx - xf, fy = gy - yf;
#pragma unroll
        for (int j = 0; j < 4; j++) {
            int xi = x0 + (j & 1), yi = y0 + (j >> 1);
            float vv = (xi >= 0 && xi < 512 && yi >= 0 && yi < 512) ? 1.0f : 0.0f;
            offB[tid][j] = min(max(yi, 0), 511) * 512 + min(max(xi, 0), 511);
            wB[tid][j]   = ((j & 1) ? fx : 1.0f - fx) * ((j >> 1) ? fy : 1.0f - fy) * vv;
        }
    }

    // stage transposed weight (coalesced float4 copy)
    {
        const float4* w4 = (const float4*)g_wT;
        float4* d4 = (float4*)wsh;
#pragma unroll
        for (int i = 0; i < 24; i++)
            d4[i * 256 + tid] = __ldg(w4 + i * 256 + tid);
    }
    __syncthreads();

    if (is_cov) {
        // pure coalesced copy of precomputed cov features
        const float* src = g_covfeat + (size_t)b * C_FEAT * NCOV + (tile - 12) * TILE;
#pragma unroll
        for (int i = 0; i < 12; i++) {
            int v = i * 256 + tid;
            int p = v & 15, c = v >> 4;
            fsh[c * FPAD + p] = __ldg(src + c * NCOV + p);
        }
    } else {
        const int* sel = g_selidx + b * BETA_N + tile * TILE;
        // coarse (cached)
#pragma unroll
        for (int i = 0; i < 8; i++) {
            int v = i * 256 + tid;
            int p = v & 15, c = v >> 4;
            fsh[c * FPAD + p] = __ldg(g_coarse + ((size_t)b * KN + sel[p]) * C_OUT + c);
        }
        // res2 gather
#pragma unroll 4
        for (int i = 0; i < 4; i++) {
            int v = i * 256 + tid;
            int p = v & 15, c = v >> 4;
            const float* plane = res2 + (size_t)(b * C_RES + c) * HW_RES;
            float r =        wB[p][0] * __ldg(plane + offB[p][0]);
            r = fmaf(wB[p][1], __ldg(plane + offB[p][1]), r);
            r = fmaf(wB[p][2], __ldg(plane + offB[p][2]), r);
            r = fmaf(wB[p][3], __ldg(plane + offB[p][3]), r);
            fsh[(C_OUT + c) * FPAD + p] = r;
        }
    }
    __syncthreads();

    // GEMV: thread = (o, pg) ; 8 points each, float4 feat reads
    int o = tid & 127, pg = tid >> 7;
    float acc[8];
    float bv = __ldg(bias + o);
#pragma unroll
    for (int i = 0; i < 8; i++) acc[i] = bv;

    const float4* f4base = (const float4*)(fsh + pg * 8);
#pragma unroll 4
    for (int c = 0; c < C_FEAT; c++) {
        float w = wsh[c * C_OUT + o];
        float4 fa = f4base[c * 4];       // fsh + c*16 + pg*8
        float4 fb = f4base[c * 4 + 1];
        acc[0] = fmaf(w, fa.x, acc[0]);
        acc[1] = fmaf(w, fa.y, acc[1]);
        acc[2] = fmaf(w, fa.z, acc[2]);
        acc[3] = fmaf(w, fa.w, acc[3]);
        acc[4] = fmaf(w, fb.x, acc[4]);
        acc[5] = fmaf(w, fb.y, acc[5]);
        acc[6] = fmaf(w, fb.z, acc[6]);
        acc[7] = fmaf(w, fb.w, acc[7]);
    }

    float* rp = dout + ((size_t)b * C_OUT + o) * NPTS + tile * TILE + pg * 8;
    float4* rp4 = (float4*)rp;
    rp4[0] = make_float4(acc[0], acc[1], acc[2], acc[3]);
    rp4[1] = make_float4(acc[4], acc[5], acc[6], acc[7]);
}

// ------------------------------------------------------------------
extern "C" void kernel_launch(void* const* d_in, const int* in_sizes, int n_in,
                              void* d_out, int out_size) {
    (void)in_sizes; (void)n_in; (void)out_size;
    const float* res2      = (const float*)d_in[1];
    const float* outp      = (const float*)d_in[2];
    const float* rand_over = (const float*)d_in[3];
    const float* rand_cov  = (const float*)d_in[4];
    const float* weight    = (const float*)d_in[5];
    const float* bias      = (const float*)d_in[6];
    float* dout = (float*)d_out;

    unc_kernel<<<dim3(113, B), 256>>>(outp, res2, rand_over, rand_cov, weight);
    sort_kernel<<<B, 1024>>>(rand_over, rand_cov, dout);

    cudaFuncSetAttribute(rend_kernel, cudaFuncAttributeMaxDynamicSharedMemorySize,
                         SMEM_BYTES);
    rend_kernel<<<dim3(16, B), 256, SMEM_BYTES>>>(res2, bias, dout);
}